// round 17
// baseline (speedup 1.0000x reference)
#include <cuda_runtime.h>

#define BATCH 64
#define NJ 21
#define BJ (BATCH * NJ)        // 1344
#define IMG 256
#define MPB 4                  // maps per block (128-deep store stream/thread)

// w[d] = exp(-d^2 / (2 * 2.5^2)) = exp(-d^2 / 12.5), d = 0..5
__constant__ float c_w[6] = {
    1.0f,
    0.92311634638663580f,   // exp(-0.08)
    0.72614903707369090f,   // exp(-0.32)
    0.48675225595997170f,   // exp(-0.72)
    0.27803730045319410f,   // exp(-1.28)
    0.13533528323661270f    // exp(-2.00)
};

// One block = FOUR (batch, joint) 256x256 maps (128-deep store stream/thread).
// 512 threads, each thread writes 128 float4 (lane-contiguous per store,
// 8 KB contiguous per unrolled step). __stcg: L2 write-back, L1 bypass.
// Threads 0..3 compute the four fisheye seeds in double, in parallel (matches
// jnp round-half-to-even exactly; avoids trig via cos(phi)=x/rho, sin=y/rho).
__global__ void __launch_bounds__(512) hm_kernel(float4* __restrict__ out,
                                                 const float* __restrict__ joint) {
    __shared__ int2 s_seed[MPB];

    const unsigned bj0 = blockIdx.x * MPB;

    if (threadIdx.x < MPB) {
        const unsigned bj = bj0 + threadIdx.x;
        double x = (double)joint[bj * 3 + 0];
        double y = (double)joint[bj * 3 + 1];
        double z = (double)joint[bj * 3 + 2];
        double rho = sqrt(x * x + y * y);
        double theta = atan2(rho, z);
        double r = 128.0 * theta / 1.5707963267948966;  // RADIUS * theta / (pi/2)
        double cphi, sphi;
        if (rho > 0.0) { cphi = x / rho; sphi = y / rho; }
        else           { cphi = 1.0;     sphi = 0.0;     }
        int sx = (int)rint(128.0 + r * cphi);
        int sy = (int)rint(128.0 + r * sphi);
        sx = min(max(sx, 0), IMG - 1);
        sy = min(max(sy, 0), IMG - 1);
        s_seed[threadIdx.x] = make_int2(sx, sy);
    }
    __syncthreads();

    const unsigned tid = threadIdx.x;
    const unsigned x0  = (tid & 63u) << 2;      // column of this thread's float4
    const int      y_first = (int)(tid >> 6);   // row at k=0; +8 per k

#pragma unroll
    for (int m = 0; m < MPB; m++) {
        const int2 s = s_seed[m];

        // Column weights: invariant across all 32 rows this thread touches.
        float4 wx;
        {
            float* wxp = reinterpret_cast<float*>(&wx);
#pragma unroll
            for (int k = 0; k < 4; k++) {
                int dx  = (int)(x0 + k) - s.x;
                int adx = dx < 0 ? -dx : dx;
                wxp[k] = (adx <= 5) ? c_w[adx] : 0.0f;
            }
        }

        float4* o = out + (size_t)(bj0 + m) * (IMG * IMG / 4) + tid;

#pragma unroll
        for (int k = 0; k < 32; k++) {
            int y   = y_first + k * 8;
            int dy  = y - s.y;
            int ady = dy < 0 ? -dy : dy;
            float wy = (ady <= 5) ? c_w[ady] : 0.0f;
            __stcg(o + (size_t)k * 512,
                   make_float4(wy * wx.x, wy * wx.y, wy * wx.z, wy * wx.w));
        }
    }
}

extern "C" void kernel_launch(void* const* d_in, const int* in_sizes, int n_in,
                              void* d_out, int out_size) {
    const float* joint = (const float*)d_in[0];
    // 336 blocks, four maps each, 512 threads
    hm_kernel<<<BJ / MPB, 512>>>((float4*)d_out, joint);
}